// round 14
// baseline (speedup 1.0000x reference)
#include <cuda_runtime.h>
#include <cuda_bf16.h>
#include <cstddef>

#define BB 2048
#define NN 512
#define XX 32
#define HH 64
#define TILE_B 16
#define THREADS 512
#define NBLK (BB / TILE_B)   /* 128 */
#define AXP 40               /* x operand pitch (bf16) */
#define AHP 72               /* h operand pitch (bf16) */
#define GP 66                /* f32 pitch in g_sh */

__device__ __forceinline__ float sigmoidf_fast(float x) {
    return __fdividef(1.0f, 1.0f + __expf(-x));
}
__device__ __forceinline__ float tanhf_fast(float x) {
    return __fdividef(2.0f, 1.0f + __expf(-2.0f * x)) - 1.0f;
}
__device__ __forceinline__ unsigned bfpack(__nv_bfloat16 a, __nv_bfloat16 b) {
    __nv_bfloat162 t;
    t.x = a; t.y = b;
    return *reinterpret_cast<unsigned*>(&t);
}
__device__ __forceinline__ void bsplit(float v, __nv_bfloat16& bh, __nv_bfloat16& bl) {
    bh = __float2bfloat16_rn(v);
    bl = __float2bfloat16_rn(v - __bfloat162float(bh));
}
__device__ __forceinline__ void mma16816(float* c, const unsigned* a, const unsigned* b) {
    asm volatile(
        "mma.sync.aligned.m16n8k16.row.col.f32.bf16.bf16.f32 "
        "{%0,%1,%2,%3}, {%4,%5,%6,%7}, {%8,%9}, {%0,%1,%2,%3};"
        : "+f"(c[0]), "+f"(c[1]), "+f"(c[2]), "+f"(c[3])
        : "r"(a[0]), "r"(a[1]), "r"(a[2]), "r"(a[3]), "r"(b[0]), "r"(b[1]));
}

__global__ void __launch_bounds__(THREADS, 1)
timelstm_tc_kernel(const float* __restrict__ x,
                   const float* __restrict__ ig_w_c, const float* __restrict__ ig_w_h,
                   const float* __restrict__ ig_w_x, const float* __restrict__ ig_b,
                   const float* __restrict__ fg_w_c, const float* __restrict__ fg_w_h,
                   const float* __restrict__ fg_w_x, const float* __restrict__ fg_b,
                   const float* __restrict__ in_w_h, const float* __restrict__ in_w_x,
                   const float* __restrict__ in_b,
                   const float* __restrict__ og_w_cn, const float* __restrict__ og_w_h,
                   const float* __restrict__ og_w_x, const float* __restrict__ og_b,
                   float* __restrict__ out)
{
    // ping-pong operands
    __shared__ __align__(16) __nv_bfloat16 Axhi[2][TILE_B][AXP];
    __shared__ __align__(16) __nv_bfloat16 Axlo[2][TILE_B][AXP];
    __shared__ __align__(16) __nv_bfloat16 Ahhi[2][TILE_B][AHP];
    __shared__ __align__(16) __nv_bfloat16 Ahlo[2][TILE_B][AHP];
    __shared__ float g_sh[2][4][TILE_B][GP];   // [khalf][gate][row][ch]

    const int tid  = threadIdx.x;
    const int b0   = blockIdx.x * TILE_B;
    const int warp = tid >> 5;
    const int lane = tid & 31;
    const int gate  = warp >> 2;        // 0 ig, 1 fg, 2 in, 3 og
    const int nhalf = (warp >> 1) & 1;  // which 32 output channels
    const int khalf = warp & 1;         // k-slice
    const int jn = lane >> 2;
    const int jk = (lane & 3) * 2;

    const float *Wh, *Wx;
    if (gate == 0)      { Wh = ig_w_h; Wx = ig_w_x; }
    else if (gate == 1) { Wh = fg_w_h; Wx = fg_w_x; }
    else if (gate == 2) { Wh = in_w_h; Wx = in_w_x; }
    else                { Wh = og_w_h; Wx = og_w_x; }

    // my three global k-tiles: x-tile khalf, h-tiles 2+khalf and 4+khalf
    const int kts0 = khalf;          // x
    const int kts1 = 2 + khalf;      // h
    const int kts2 = 4 + khalf;      // h

    // ---- B fragments (3 k-tiles x 4 n-tiles, hi+lo) ----
    unsigned Bh[3][4][2], Bl[3][4][2];
    #pragma unroll
    for (int l = 0; l < 3; l++) {
        const int ktg = (l == 0) ? kts0 : (l == 1 ? kts1 : kts2);
        #pragma unroll
        for (int nt = 0; nt < 4; nt++) {
            const int ch = nhalf * 32 + nt * 8 + jn;
            #pragma unroll
            for (int r = 0; r < 2; r++) {
                const int k0 = ktg * 16 + jk + r * 8;
                float v0 = (k0 < 32)     ? Wx[ch * XX + k0]     : Wh[ch * HH + (k0 - 32)];
                float v1 = (k0 + 1 < 32) ? Wx[ch * XX + k0 + 1] : Wh[ch * HH + (k0 + 1 - 32)];
                __nv_bfloat16 h0, l0, h1, l1;
                bsplit(v0, h0, l0);
                bsplit(v1, h1, l1);
                Bh[l][nt][r] = bfpack(h0, h1);
                Bl[l][nt][r] = bfpack(l0, l1);
            }
        }
    }

    // ---- phase-B constants: row rg, channels pc, pc+1 ----
    const int rg = tid >> 5;          // 0..15
    const int pc = (tid & 31) * 2;    // 0..62 even
    float bI[2], bF[2], bN[2], bO[2], wic[2], wfc[2], woc[2];
    #pragma unroll
    for (int c = 0; c < 2; c++) {
        bI[c] = ig_b[pc + c];  bF[c] = fg_b[pc + c];
        bN[c] = in_b[pc + c];  bO[c] = og_b[pc + c];
        wic[c] = ig_w_c[pc + c]; wfc[c] = fg_w_c[pc + c]; woc[c] = og_w_cn[pc + c];
    }
    float cm[2] = {0.0f, 0.0f};

    // x loader: 1 value/thread (16 rows x 32 cols = 512)
    const int xrow = tid >> 5;
    const int xk   = tid & 31;
    const float* xptr = x + ((size_t)(b0 + xrow) * NN) * XX + xk;

    // ---- prologue: zero Ah[0]; deposit x(0) ----
    for (int i = tid; i < TILE_B * AHP; i += THREADS) {
        (&Ahhi[0][0][0])[i] = __float2bfloat16_rn(0.0f);
        (&Ahlo[0][0][0])[i] = __float2bfloat16_rn(0.0f);
    }
    {
        float xv = xptr[0];
        __nv_bfloat16 h0, l0;
        bsplit(xv, h0, l0);
        Axhi[0][xrow][xk] = h0;
        Axlo[0][xrow][xk] = l0;
    }
    __syncthreads();

    float acc[4][4];
    unsigned a[4];

    // x-contrib(0): my single x-tile on Ax[0]
    #pragma unroll
    for (int nt = 0; nt < 4; nt++)
        #pragma unroll
        for (int i = 0; i < 4; i++) acc[nt][i] = 0.0f;
    {
        const int kc = kts0 * 16 + jk;
        a[0] = *reinterpret_cast<const unsigned*>(&Axhi[0][jn][kc]);
        a[1] = *reinterpret_cast<const unsigned*>(&Axhi[0][jn + 8][kc]);
        a[2] = *reinterpret_cast<const unsigned*>(&Axhi[0][jn][kc + 8]);
        a[3] = *reinterpret_cast<const unsigned*>(&Axhi[0][jn + 8][kc + 8]);
        #pragma unroll
        for (int nt = 0; nt < 4; nt++) mma16816(acc[nt], a, Bh[0][nt]);
        #pragma unroll
        for (int nt = 0; nt < 4; nt++) mma16816(acc[nt], a, Bl[0][nt]);
        a[0] = *reinterpret_cast<const unsigned*>(&Axlo[0][jn][kc]);
        a[1] = *reinterpret_cast<const unsigned*>(&Axlo[0][jn + 8][kc]);
        a[2] = *reinterpret_cast<const unsigned*>(&Axlo[0][jn][kc + 8]);
        a[3] = *reinterpret_cast<const unsigned*>(&Axlo[0][jn + 8][kc + 8]);
        #pragma unroll
        for (int nt = 0; nt < 4; nt++) mma16816(acc[nt], a, Bh[0][nt]);
    }
    float xn = xptr[XX];   // x(1)

    for (int t = 0; t < NN; t++) {
        const int buf  = t & 1;
        const int nbuf = buf ^ 1;

        // ---- W1: deposit x(t+1); h-MMA on my two h-tiles ----
        {
            __nv_bfloat16 h0, l0;
            bsplit(xn, h0, l0);
            Axhi[nbuf][xrow][xk] = h0;
            Axlo[nbuf][xrow][xk] = l0;
        }

        #pragma unroll
        for (int l = 1; l < 3; l++) {
            const int ktg = (l == 1) ? kts1 : kts2;
            const int hc = (ktg - 2) * 16 + jk;
            a[0] = *reinterpret_cast<const unsigned*>(&Ahhi[buf][jn][hc]);
            a[1] = *reinterpret_cast<const unsigned*>(&Ahhi[buf][jn + 8][hc]);
            a[2] = *reinterpret_cast<const unsigned*>(&Ahhi[buf][jn][hc + 8]);
            a[3] = *reinterpret_cast<const unsigned*>(&Ahhi[buf][jn + 8][hc + 8]);
            #pragma unroll
            for (int nt = 0; nt < 4; nt++) mma16816(acc[nt], a, Bh[l][nt]);
            #pragma unroll
            for (int nt = 0; nt < 4; nt++) mma16816(acc[nt], a, Bl[l][nt]);
        }
        #pragma unroll
        for (int l = 1; l < 3; l++) {
            const int ktg = (l == 1) ? kts1 : kts2;
            const int hc = (ktg - 2) * 16 + jk;
            a[0] = *reinterpret_cast<const unsigned*>(&Ahlo[buf][jn][hc]);
            a[1] = *reinterpret_cast<const unsigned*>(&Ahlo[buf][jn + 8][hc]);
            a[2] = *reinterpret_cast<const unsigned*>(&Ahlo[buf][jn][hc + 8]);
            a[3] = *reinterpret_cast<const unsigned*>(&Ahlo[buf][jn + 8][hc + 8]);
            #pragma unroll
            for (int nt = 0; nt < 4; nt++) mma16816(acc[nt], a, Bh[l][nt]);
        }

        // scatter partial gate sums: g_sh[khalf][gate]
        #pragma unroll
        for (int nt = 0; nt < 4; nt++) {
            const int ch = nhalf * 32 + nt * 8 + jk;
            *reinterpret_cast<float2*>(&g_sh[khalf][gate][jn][ch]) =
                make_float2(acc[nt][0], acc[nt][1]);
            *reinterpret_cast<float2*>(&g_sh[khalf][gate][jn + 8][ch]) =
                make_float2(acc[nt][2], acc[nt][3]);
        }
        __syncthreads();   // B1: g_sh + x(t+1) deposits visible

        // ---- W2: phase B (MUFU) overlapped with x-MMA(t+1) (tensor) ----
        if (t + 2 < NN) xn = xptr[(size_t)(t + 2) * XX];

        if (t + 1 < NN) {
            #pragma unroll
            for (int nt = 0; nt < 4; nt++)
                #pragma unroll
                for (int i = 0; i < 4; i++) acc[nt][i] = 0.0f;
            const int kc = kts0 * 16 + jk;
            a[0] = *reinterpret_cast<const unsigned*>(&Axhi[nbuf][jn][kc]);
            a[1] = *reinterpret_cast<const unsigned*>(&Axhi[nbuf][jn + 8][kc]);
            a[2] = *reinterpret_cast<const unsigned*>(&Axhi[nbuf][jn][kc + 8]);
            a[3] = *reinterpret_cast<const unsigned*>(&Axhi[nbuf][jn + 8][kc + 8]);
            #pragma unroll
            for (int nt = 0; nt < 4; nt++) mma16816(acc[nt], a, Bh[0][nt]);
            #pragma unroll
            for (int nt = 0; nt < 4; nt++) mma16816(acc[nt], a, Bl[0][nt]);
            a[0] = *reinterpret_cast<const unsigned*>(&Axlo[nbuf][jn][kc]);
            a[1] = *reinterpret_cast<const unsigned*>(&Axlo[nbuf][jn + 8][kc]);
            a[2] = *reinterpret_cast<const unsigned*>(&Axlo[nbuf][jn][kc + 8]);
            a[3] = *reinterpret_cast<const unsigned*>(&Axlo[nbuf][jn + 8][kc + 8]);
            #pragma unroll
            for (int nt = 0; nt < 4; nt++) mma16816(acc[nt], a, Bh[0][nt]);
        }

        // phase B: sum k-halves, activations, state update (1 row x 2 ch)
        {
            float2 gI0 = *reinterpret_cast<const float2*>(&g_sh[0][0][rg][pc]);
            float2 gI1 = *reinterpret_cast<const float2*>(&g_sh[1][0][rg][pc]);
            float2 gF0 = *reinterpret_cast<const float2*>(&g_sh[0][1][rg][pc]);
            float2 gF1 = *reinterpret_cast<const float2*>(&g_sh[1][1][rg][pc]);
            float2 gN0 = *reinterpret_cast<const float2*>(&g_sh[0][2][rg][pc]);
            float2 gN1 = *reinterpret_cast<const float2*>(&g_sh[1][2][rg][pc]);
            float2 gO0 = *reinterpret_cast<const float2*>(&g_sh[0][3][rg][pc]);
            float2 gO1 = *reinterpret_cast<const float2*>(&g_sh[1][3][rg][pc]);
            float gI[2] = {gI0.x + gI1.x, gI0.y + gI1.y};
            float gF[2] = {gF0.x + gF1.x, gF0.y + gF1.y};
            float gN[2] = {gN0.x + gN1.x, gN0.y + gN1.y};
            float gO[2] = {gO0.x + gO1.x, gO0.y + gO1.y};

            float hnew[2];
            #pragma unroll
            for (int c = 0; c < 2; c++) {
                const float cmv = cm[c];
                const float ig  = sigmoidf_fast(wic[c] * cmv + gI[c] + bI[c]);
                const float fg  = sigmoidf_fast(wfc[c] * cmv + gF[c] + bF[c]);
                const float inn = tanhf_fast(gN[c] + bN[c]);
                const float cmn = fg * cmv + ig * inn;
                const float og  = sigmoidf_fast(woc[c] * cmn + gO[c] + bO[c]);
                hnew[c] = og * tanhf_fast(cmn);
                cm[c] = cmn;
            }
            __nv_bfloat16 h0, l0, h1, l1;
            bsplit(hnew[0], h0, l0);
            bsplit(hnew[1], h1, l1);
            *reinterpret_cast<unsigned*>(&Ahhi[nbuf][rg][pc]) = bfpack(h0, h1);
            *reinterpret_cast<unsigned*>(&Ahlo[nbuf][rg][pc]) = bfpack(l0, l1);

            if (t == NN - 1) {
                *reinterpret_cast<float2*>(&out[(size_t)(b0 + rg) * HH + pc]) =
                    make_float2(hnew[0], hnew[1]);
            }
        }
        __syncthreads();   // B2: h(t+1) ready; x-MMA reads complete
    }
}

extern "C" void kernel_launch(void* const* d_in, const int* in_sizes, int n_in,
                              void* d_out, int out_size) {
    const float* x       = (const float*)d_in[0];
    const float* ig_w_c  = (const float*)d_in[1];
    const float* ig_w_h  = (const float*)d_in[2];
    const float* ig_w_x  = (const float*)d_in[3];
    const float* ig_b    = (const float*)d_in[4];
    const float* fg_w_c  = (const float*)d_in[5];
    const float* fg_w_h  = (const float*)d_in[6];
    const float* fg_w_x  = (const float*)d_in[7];
    const float* fg_b    = (const float*)d_in[8];
    const float* in_w_h  = (const float*)d_in[9];
    const float* in_w_x  = (const float*)d_in[10];
    const float* in_b    = (const float*)d_in[11];
    const float* og_w_cn = (const float*)d_in[12];
    const float* og_w_h  = (const float*)d_in[13];
    const float* og_w_x  = (const float*)d_in[14];
    const float* og_b    = (const float*)d_in[15];
    float* out = (float*)d_out;

    timelstm_tc_kernel<<<NBLK, THREADS>>>(
        x, ig_w_c, ig_w_h, ig_w_x, ig_b,
        fg_w_c, fg_w_h, fg_w_x, fg_b,
        in_w_h, in_w_x, in_b,
        og_w_cn, og_w_h, og_w_x, og_b, out);
}